// round 9
// baseline (speedup 1.0000x reference)
#include <cuda_runtime.h>
#include <cuda_bf16.h>

#define IN_F 128
#define HID 128
#define NCTX 32
#define ALPHA 0.2f
#define NEG_INF -9000000000000000.0f
#define MAXN 20000

// Scratch (device globals — no allocation allowed)
__device__ __align__(16) float g_u_i[IN_F];       // W_i @ a_i
__device__ __align__(16) float g_u_j[IN_F];       // W_j @ a_j
__device__ float g_bias;
__device__ float g_s_i[MAXN];
__device__ float g_s_j[MAXN];
__device__ __align__(16) float g_feat[(size_t)MAXN * HID]; // attn-weighted raw-feature sums

// packed f32x2 helpers (Blackwell FFMA2 via PTX)
__device__ __forceinline__ unsigned long long dup2(float a) {
    unsigned long long r;
    asm("mov.b64 %0, {%1, %1};" : "=l"(r) : "f"(a));
    return r;
}
__device__ __forceinline__ void fma2(unsigned long long& d,
                                     unsigned long long a, unsigned long long b) {
    asm("fma.rn.f32x2 %0, %1, %2, %0;" : "+l"(d) : "l"(a), "l"(b));
}
__device__ __forceinline__ void unpk2(unsigned long long v, float& x, float& y) {
    asm("mov.b64 {%0, %1}, %2;" : "=f"(x), "=f"(y) : "l"(v));
}

// ---------------------------------------------------------------------------
// K1: fold attention vectors through weights — one warp per output element.
// ---------------------------------------------------------------------------
__global__ void prep_kernel(const float* __restrict__ W_i,
                            const float* __restrict__ W_j,
                            const float* __restrict__ a_w,
                            const float* __restrict__ a_b) {
    int warp = blockIdx.x * (blockDim.x >> 5) + (threadIdx.x >> 5);  // 0..255
    int lane = threadIdx.x & 31;
    const float* W  = (warp < 128) ? W_i : W_j;
    const float* av = (warp < 128) ? a_w : a_w + HID;
    int f = warp & 127;
    float4 w4 = ((const float4*)W)[f * 32 + lane];
    float4 a4 = ((const float4*)av)[lane];
    float s = w4.x * a4.x + w4.y * a4.y + w4.z * a4.z + w4.w * a4.w;
    #pragma unroll
    for (int o = 16; o; o >>= 1) s += __shfl_xor_sync(0xffffffffu, s, o);
    if (lane == 0) {
        if (warp < 128) g_u_i[f] = s; else g_u_j[f] = s;
    }
    if (warp == 0 && lane == 0) g_bias = a_b[0];
}

// ---------------------------------------------------------------------------
// K2: per-node scalar scores.  s_i[n] = h[n].u_i ; s_j[n] = h[n].u_j
// ---------------------------------------------------------------------------
__global__ void score_kernel(const float* __restrict__ h_i, int N) {
    int warp = blockIdx.x * (blockDim.x >> 5) + (threadIdx.x >> 5);
    int lane = threadIdx.x & 31;
    if (warp >= N) return;
    const float4* h4 = (const float4*)h_i;
    float4 v  = h4[(size_t)warp * 32 + lane];
    float4 ui = ((const float4*)g_u_i)[lane];
    float4 uj = ((const float4*)g_u_j)[lane];
    float a = v.x * ui.x + v.y * ui.y + v.z * ui.z + v.w * ui.w;
    float b = v.x * uj.x + v.y * uj.y + v.z * uj.z + v.w * uj.w;
    #pragma unroll
    for (int o = 16; o; o >>= 1) {
        a += __shfl_xor_sync(0xffffffffu, a, o);
        b += __shfl_xor_sync(0xffffffffu, b, o);
    }
    if (lane == 0) {
        g_s_i[warp] = a;
        g_s_j[warp] = b;
    }
}

// ---------------------------------------------------------------------------
// K3: gather + leaky-relu + softmax + attention-weighted raw-feature sum.
// One warp per node.
// ---------------------------------------------------------------------------
__global__ void gather_kernel(const float* __restrict__ h_i,
                              const int* __restrict__ ctx, int N) {
    int warp = blockIdx.x * (blockDim.x >> 5) + (threadIdx.x >> 5);
    int lane = threadIdx.x & 31;
    if (warp >= N) return;

    int j = ctx[(size_t)warp * NCTX + lane];
    bool valid = (j >= 0);

    float sj = valid ? g_s_j[j] : 0.f;
    float e = g_s_i[warp] + sj + g_bias;
    e = (e > 0.f) ? e : ALPHA * e;       // leaky relu
    e = valid ? e : NEG_INF;             // mask

    float m = e;
    #pragma unroll
    for (int o = 16; o; o >>= 1) m = fmaxf(m, __shfl_xor_sync(0xffffffffu, m, o));
    float p = valid ? __expf(e - m) : 0.f;
    float s = p;
    #pragma unroll
    for (int o = 16; o; o >>= 1) s += __shfl_xor_sync(0xffffffffu, s, o);
    float w = p * ((s > 0.f) ? (1.f / s) : 0.f);

    float4 acc = make_float4(0.f, 0.f, 0.f, 0.f);
    const float4* h4 = (const float4*)h_i;
    #pragma unroll
    for (int c = 0; c < NCTX; c++) {
        float wc = __shfl_sync(0xffffffffu, w, c);
        int jc   = __shfl_sync(0xffffffffu, j, c);
        if (jc >= 0) {
            float4 v = h4[(size_t)jc * 32 + lane];
            acc.x = fmaf(wc, v.x, acc.x);
            acc.y = fmaf(wc, v.y, acc.y);
            acc.z = fmaf(wc, v.z, acc.z);
            acc.w = fmaf(wc, v.w, acc.w);
        }
    }
    ((float4*)g_feat)[(size_t)warp * 32 + lane] = acc;
}

// ---------------------------------------------------------------------------
// K4 (v7): out = g_feat @ W_j.  128 thr / 4 warps / 32 rows per block.
// Warp = 16 rows x 64 cols; lane owns a 2-col pair.
// W (b) lives in REGISTERS, loaded per 16-k chunk with coalesced LDG.64
// (L2-resident, hidden under >=512 fma-cycles of compute per chunk).
// A (a) comes from smem as pre-duplicated {a,a} pairs packed 2-k per 16B:
// one broadcast LDS.128 feeds TWO FFMA2 per row.
// Per 2k per warp: 16 LDS.128 + 32 FFMA2  ->  LSU 32 cyc < fma 64 cyc.
// ---------------------------------------------------------------------------
__global__ __launch_bounds__(128) void out_gemm_kernel(
    const float* __restrict__ Wj, float* __restrict__ out, int N) {
    __shared__ ulonglong2 adup2[32][64];   // 32KB: [row][kpair] = {dup(a[2p]),dup(a[2p+1])}

    int row0 = blockIdx.x * 32;
    int tid  = threadIdx.x;
    int warp = tid >> 5;
    int lane = tid & 31;
    int rbase = (warp & 1) * 16;                // rows [rbase, rbase+16)
    int cbase = (warp >> 1) * 64 + lane * 2;    // 2-col pair (even)

    const float4* g4 = (const float4*)g_feat;

    // Fill adup2 once: rows [row0..row0+32) x 128 k, duplicated + k-paired.
    #pragma unroll
    for (int idx = tid; idx < 32 * 32; idx += 128) {
        int r = idx >> 5, q = idx & 31;          // q = float4 chunk (4 k)
        int gr = row0 + r;
        float4 v = make_float4(0.f, 0.f, 0.f, 0.f);
        if (gr < N) v = g4[(size_t)gr * 32 + q];
        adup2[r][q * 2]     = make_ulonglong2(dup2(v.x), dup2(v.y));
        adup2[r][q * 2 + 1] = make_ulonglong2(dup2(v.z), dup2(v.w));
    }
    __syncthreads();

    unsigned long long acc[16];
    #pragma unroll
    for (int r = 0; r < 16; r++) acc[r] = 0ull;

    const unsigned long long* wp = (const unsigned long long*)Wj;  // [k*64 + col/2]

    #pragma unroll 1
    for (int kc = 0; kc < 8; kc++) {
        // W chunk -> registers (16 coalesced LDG.64, MLP=16)
        unsigned long long wreg[16];
        #pragma unroll
        for (int kk = 0; kk < 16; kk++)
            wreg[kk] = wp[(size_t)(kc * 16 + kk) * 64 + (cbase >> 1)];

        #pragma unroll
        for (int p = 0; p < 8; p++) {            // k-pair within chunk
            #pragma unroll
            for (int r = 0; r < 16; r++) {
                ulonglong2 a2 = adup2[rbase + r][kc * 8 + p];  // broadcast LDS.128
                fma2(acc[r], a2.x, wreg[2 * p]);
                fma2(acc[r], a2.y, wreg[2 * p + 1]);
            }
        }
    }

    #pragma unroll
    for (int r = 0; r < 16; r++) {
        int gr = row0 + rbase + r;
        if (gr < N) {
            float2 o;
            unpk2(acc[r], o.x, o.y);
            *(float2*)&out[(size_t)gr * 128 + cbase] = o;
        }
    }
}

// ---------------------------------------------------------------------------
extern "C" void kernel_launch(void* const* d_in, const int* in_sizes, int n_in,
                              void* d_out, int out_size) {
    const float* h_i = (const float*)d_in[0];
    const int*   ctx = (const int*)d_in[1];     // int32
    const float* W_i = (const float*)d_in[2];
    const float* W_j = (const float*)d_in[3];
    const float* a_w = (const float*)d_in[4];
    const float* a_b = (const float*)d_in[5];
    float* out = (float*)d_out;

    int N = in_sizes[0] / IN_F;

    prep_kernel<<<32, 256>>>(W_i, W_j, a_w, a_b);

    int blocks = (N + 7) / 8;
    score_kernel<<<blocks, 256>>>(h_i, N);
    gather_kernel<<<blocks, 256>>>(h_i, ctx, N);

    int gemm_blocks = (N + 31) / 32;
    out_gemm_kernel<<<gemm_blocks, 128>>>(W_j, out, N);
}

// round 10
// speedup vs baseline: 1.3459x; 1.3459x over previous
#include <cuda_runtime.h>
#include <cuda_bf16.h>
#include <cstdint>

#define IN_F 128
#define HID 128
#define NCTX 32
#define ALPHA 0.2f
#define NEG_INF -9000000000000000.0f
#define MAXN 20000
#define MAXR 20032   // MAXN rounded up to 64

// Scratch (device globals — no allocation allowed)
__device__ __align__(16) float g_u_i[IN_F];
__device__ __align__(16) float g_u_j[IN_F];
__device__ float g_bias;
__device__ float g_s_i[MAXN];
__device__ float g_s_j[MAXN];
__device__ __align__(16) __nv_bfloat16 g_ah[(size_t)MAXR * HID];  // A hi (bf16)
__device__ __align__(16) __nv_bfloat16 g_al[(size_t)MAXR * HID];  // A lo (bf16)
__device__ __align__(16) __nv_bfloat16 g_wh[HID * HID];           // W hi
__device__ __align__(16) __nv_bfloat16 g_wl[HID * HID];           // W lo

// ---------------------------------------------------------------------------
// mma/ldmatrix helpers
// ---------------------------------------------------------------------------
__device__ __forceinline__ uint32_t smem_u32(const void* p) {
    return (uint32_t)__cvta_generic_to_shared(p);
}
__device__ __forceinline__ void ldsm_x4(uint32_t* r, uint32_t addr) {
    asm volatile("ldmatrix.sync.aligned.m8n8.x4.shared.b16 {%0,%1,%2,%3}, [%4];"
        : "=r"(r[0]), "=r"(r[1]), "=r"(r[2]), "=r"(r[3]) : "r"(addr));
}
__device__ __forceinline__ void ldsm_x4_t(uint32_t* r, uint32_t addr) {
    asm volatile("ldmatrix.sync.aligned.m8n8.x4.trans.shared.b16 {%0,%1,%2,%3}, [%4];"
        : "=r"(r[0]), "=r"(r[1]), "=r"(r[2]), "=r"(r[3]) : "r"(addr));
}
__device__ __forceinline__ void mma16816(float* c, const uint32_t* a,
                                         uint32_t b0, uint32_t b1) {
    asm volatile(
        "mma.sync.aligned.m16n8k16.row.col.f32.bf16.bf16.f32 "
        "{%0,%1,%2,%3}, {%4,%5,%6,%7}, {%8,%9}, {%0,%1,%2,%3};"
        : "+f"(c[0]), "+f"(c[1]), "+f"(c[2]), "+f"(c[3])
        : "r"(a[0]), "r"(a[1]), "r"(a[2]), "r"(a[3]), "r"(b0), "r"(b1));
}

// ---------------------------------------------------------------------------
// K1: fold attention vectors through weights — one warp per output element.
// ---------------------------------------------------------------------------
__global__ void prep_kernel(const float* __restrict__ W_i,
                            const float* __restrict__ W_j,
                            const float* __restrict__ a_w,
                            const float* __restrict__ a_b) {
    int warp = blockIdx.x * (blockDim.x >> 5) + (threadIdx.x >> 5);  // 0..255
    int lane = threadIdx.x & 31;
    const float* W  = (warp < 128) ? W_i : W_j;
    const float* av = (warp < 128) ? a_w : a_w + HID;
    int f = warp & 127;
    float4 w4 = ((const float4*)W)[f * 32 + lane];
    float4 a4 = ((const float4*)av)[lane];
    float s = w4.x * a4.x + w4.y * a4.y + w4.z * a4.z + w4.w * a4.w;
    #pragma unroll
    for (int o = 16; o; o >>= 1) s += __shfl_xor_sync(0xffffffffu, s, o);
    if (lane == 0) {
        if (warp < 128) g_u_i[f] = s; else g_u_j[f] = s;
    }
    if (warp == 0 && lane == 0) g_bias = a_b[0];
}

// ---------------------------------------------------------------------------
// K1b: split W_j into bf16 hi/lo.
// ---------------------------------------------------------------------------
__global__ void wsplit_kernel(const float* __restrict__ W_j) {
    int i = blockIdx.x * blockDim.x + threadIdx.x;   // 16384 total
    float v = W_j[i];
    __nv_bfloat16 h = __float2bfloat16(v);
    g_wh[i] = h;
    g_wl[i] = __float2bfloat16(v - __bfloat162float(h));
}

// ---------------------------------------------------------------------------
// K2: per-node scalar scores.
// ---------------------------------------------------------------------------
__global__ void score_kernel(const float* __restrict__ h_i, int N) {
    int warp = blockIdx.x * (blockDim.x >> 5) + (threadIdx.x >> 5);
    int lane = threadIdx.x & 31;
    if (warp >= N) return;
    const float4* h4 = (const float4*)h_i;
    float4 v  = h4[(size_t)warp * 32 + lane];
    float4 ui = ((const float4*)g_u_i)[lane];
    float4 uj = ((const float4*)g_u_j)[lane];
    float a = v.x * ui.x + v.y * ui.y + v.z * ui.z + v.w * ui.w;
    float b = v.x * uj.x + v.y * uj.y + v.z * uj.z + v.w * uj.w;
    #pragma unroll
    for (int o = 16; o; o >>= 1) {
        a += __shfl_xor_sync(0xffffffffu, a, o);
        b += __shfl_xor_sync(0xffffffffu, b, o);
    }
    if (lane == 0) {
        g_s_i[warp] = a;
        g_s_j[warp] = b;
    }
}

// ---------------------------------------------------------------------------
// K3: gather + softmax + weighted raw-feature sum -> split bf16 A (hi/lo).
// One warp per node.
// ---------------------------------------------------------------------------
__global__ void gather_kernel(const float* __restrict__ h_i,
                              const int* __restrict__ ctx, int N) {
    int warp = blockIdx.x * (blockDim.x >> 5) + (threadIdx.x >> 5);
    int lane = threadIdx.x & 31;
    if (warp >= N) return;

    int j = ctx[(size_t)warp * NCTX + lane];
    bool valid = (j >= 0);

    float sj = valid ? g_s_j[j] : 0.f;
    float e = g_s_i[warp] + sj + g_bias;
    e = (e > 0.f) ? e : ALPHA * e;
    e = valid ? e : NEG_INF;

    float m = e;
    #pragma unroll
    for (int o = 16; o; o >>= 1) m = fmaxf(m, __shfl_xor_sync(0xffffffffu, m, o));
    float p = valid ? __expf(e - m) : 0.f;
    float s = p;
    #pragma unroll
    for (int o = 16; o; o >>= 1) s += __shfl_xor_sync(0xffffffffu, s, o);
    float w = p * ((s > 0.f) ? (1.f / s) : 0.f);

    float4 acc = make_float4(0.f, 0.f, 0.f, 0.f);
    const float4* h4 = (const float4*)h_i;
    #pragma unroll
    for (int c = 0; c < NCTX; c++) {
        float wc = __shfl_sync(0xffffffffu, w, c);
        int jc   = __shfl_sync(0xffffffffu, j, c);
        if (jc >= 0) {
            float4 v = h4[(size_t)jc * 32 + lane];
            acc.x = fmaf(wc, v.x, acc.x);
            acc.y = fmaf(wc, v.y, acc.y);
            acc.z = fmaf(wc, v.z, acc.z);
            acc.w = fmaf(wc, v.w, acc.w);
        }
    }

    __nv_bfloat16 bx = __float2bfloat16(acc.x);
    __nv_bfloat16 by = __float2bfloat16(acc.y);
    __nv_bfloat16 bz = __float2bfloat16(acc.z);
    __nv_bfloat16 bw = __float2bfloat16(acc.w);
    __nv_bfloat162* dh = (__nv_bfloat162*)&g_ah[(size_t)warp * HID + lane * 4];
    dh[0] = __halves2bfloat162(bx, by);
    dh[1] = __halves2bfloat162(bz, bw);
    __nv_bfloat162* dl = (__nv_bfloat162*)&g_al[(size_t)warp * HID + lane * 4];
    dl[0] = __halves2bfloat162(__float2bfloat16(acc.x - __bfloat162float(bx)),
                               __float2bfloat16(acc.y - __bfloat162float(by)));
    dl[1] = __halves2bfloat162(__float2bfloat16(acc.z - __bfloat162float(bz)),
                               __float2bfloat16(acc.w - __bfloat162float(bw)));
}

// ---------------------------------------------------------------------------
// K4 (v8): out = A @ W via tensor cores (bf16 split: Ah·Wh + Ah·Wl + Al·Wh).
// Block: 256 thr / 8 warps, tile 64 rows x 128 cols.
// Warp tile 16 x 64: rbase=(warp&3)*16, cbase=(warp>>2)*64.
// k chunks of 32 staged in smem; frags via ldmatrix; 48 mma per warp-chunk.
// smem rows padded for conflict-free LDSM (A: 40 bf16, B: 136 bf16).
// ---------------------------------------------------------------------------
__global__ __launch_bounds__(256) void mma_gemm_kernel(float* __restrict__ out,
                                                       int N) {
    __shared__ __align__(16) __nv_bfloat16 Ah_s[64][40];
    __shared__ __align__(16) __nv_bfloat16 Al_s[64][40];
    __shared__ __align__(16) __nv_bfloat16 Bh_s[32][136];
    __shared__ __align__(16) __nv_bfloat16 Bl_s[32][136];

    int row0 = blockIdx.x * 64;
    int tid  = threadIdx.x;
    int warp = tid >> 5;
    int lane = tid & 31;
    int rbase = (warp & 3) * 16;
    int cbase = (warp >> 2) * 64;

    float acc[8][4];
    #pragma unroll
    for (int t = 0; t < 8; t++)
        #pragma unroll
        for (int q = 0; q < 4; q++) acc[t][q] = 0.f;

    for (int kc = 0; kc < 4; kc++) {
        __syncthreads();
        // A chunk: 64 rows x 32 k.  thread: row=tid>>2, 8 bf16 at q*8.
        {
            int r = tid >> 2, q = tid & 3;
            int gr = row0 + r;
            uint4 vh = make_uint4(0, 0, 0, 0), vl = vh;
            if (gr < N) {
                vh = *(const uint4*)&g_ah[(size_t)gr * HID + kc * 32 + q * 8];
                vl = *(const uint4*)&g_al[(size_t)gr * HID + kc * 32 + q * 8];
            }
            *(uint4*)&Ah_s[r][q * 8] = vh;
            *(uint4*)&Al_s[r][q * 8] = vl;
        }
        // B chunk: 32 k-rows x 128 n.
        #pragma unroll
        for (int ii = tid; ii < 512; ii += 256) {
            int kr = ii >> 4, nq = ii & 15;
            *(uint4*)&Bh_s[kr][nq * 8] =
                *(const uint4*)&g_wh[(kc * 32 + kr) * HID + nq * 8];
            *(uint4*)&Bl_s[kr][nq * 8] =
                *(const uint4*)&g_wl[(kc * 32 + kr) * HID + nq * 8];
        }
        __syncthreads();

        #pragma unroll
        for (int ks = 0; ks < 2; ks++) {
            uint32_t ah[4], al[4];
            {
                int r = rbase + (lane & 15);
                int k = ks * 16 + (lane >> 4) * 8;
                ldsm_x4(ah, smem_u32(&Ah_s[r][k]));
                ldsm_x4(al, smem_u32(&Al_s[r][k]));
            }
            #pragma unroll
            for (int nt = 0; nt < 4; nt++) {   // 16 cols each -> 2 n8-frags
                uint32_t bh[4], bl[4];
                int k = ks * 16 + (lane & 15);
                int n = cbase + nt * 16 + (lane >> 4) * 8;
                ldsm_x4_t(bh, smem_u32(&Bh_s[k][n]));
                ldsm_x4_t(bl, smem_u32(&Bl_s[k][n]));
                mma16816(acc[2 * nt],     ah, bh[0], bh[1]);
                mma16816(acc[2 * nt],     ah, bl[0], bl[1]);
                mma16816(acc[2 * nt],     al, bh[0], bh[1]);
                mma16816(acc[2 * nt + 1], ah, bh[2], bh[3]);
                mma16816(acc[2 * nt + 1], ah, bl[2], bl[3]);
                mma16816(acc[2 * nt + 1], al, bh[2], bh[3]);
            }
        }
    }

    // epilogue: c-frag layout m16n8 -> rows gid, gid+8; cols 2*tig, 2*tig+1
    int gid = lane >> 2, tig = lane & 3;
    #pragma unroll
    for (int t = 0; t < 8; t++) {
        int c  = cbase + t * 8 + tig * 2;
        int r1 = row0 + rbase + gid;
        int r2 = r1 + 8;
        if (r1 < N) *(float2*)&out[(size_t)r1 * 128 + c] = make_float2(acc[t][0], acc[t][1]);
        if (r2 < N) *(float2*)&out[(size_t)r2 * 128 + c] = make_float2(acc[t][2], acc[t][3]);
    }
}

// ---------------------------------------------------------------------------
extern "C" void kernel_launch(void* const* d_in, const int* in_sizes, int n_in,
                              void* d_out, int out_size) {
    const float* h_i = (const float*)d_in[0];
    const int*   ctx = (const int*)d_in[1];     // int32
    const float* W_i = (const float*)d_in[2];
    const float* W_j = (const float*)d_in[3];
    const float* a_w = (const float*)d_in[4];
    const float* a_b = (const float*)d_in[5];
    float* out = (float*)d_out;

    int N = in_sizes[0] / IN_F;

    prep_kernel<<<32, 256>>>(W_i, W_j, a_w, a_b);
    wsplit_kernel<<<64, 256>>>(W_j);

    int blocks = (N + 7) / 8;
    score_kernel<<<blocks, 256>>>(h_i, N);
    gather_kernel<<<blocks, 256>>>(h_i, ctx, N);

    int gemm_blocks = (N + 63) / 64;
    mma_gemm_kernel<<<gemm_blocks, 256>>>(out, N);
}

// round 11
// speedup vs baseline: 1.3933x; 1.0352x over previous
#include <cuda_runtime.h>
#include <cuda_bf16.h>
#include <cstdint>

#define IN_F 128
#define HID 128
#define NCTX 32
#define ALPHA 0.2f
#define NEG_INF -9000000000000000.0f
#define MAXN 20000
#define MAXR 20032   // MAXN rounded up to 64

// Scratch (device globals — no allocation allowed)
__device__ __align__(16) float g_u_i[IN_F];
__device__ __align__(16) float g_u_j[IN_F];
__device__ float g_bias;
__device__ float g_s_i[MAXN];
__device__ float g_s_j[MAXN];
__device__ __align__(16) __nv_bfloat16 g_ah[(size_t)MAXR * HID];  // A hi (bf16)
__device__ __align__(16) __nv_bfloat16 g_al[(size_t)MAXR * HID];  // A lo (bf16)
__device__ __align__(16) __nv_bfloat16 g_wh[HID * HID];           // W hi
__device__ __align__(16) __nv_bfloat16 g_wl[HID * HID];           // W lo

// ---------------------------------------------------------------------------
// mma/ldmatrix helpers
// ---------------------------------------------------------------------------
__device__ __forceinline__ uint32_t smem_u32(const void* p) {
    return (uint32_t)__cvta_generic_to_shared(p);
}
__device__ __forceinline__ void ldsm_x4(uint32_t* r, uint32_t addr) {
    asm volatile("ldmatrix.sync.aligned.m8n8.x4.shared.b16 {%0,%1,%2,%3}, [%4];"
        : "=r"(r[0]), "=r"(r[1]), "=r"(r[2]), "=r"(r[3]) : "r"(addr));
}
__device__ __forceinline__ void ldsm_x4_t(uint32_t* r, uint32_t addr) {
    asm volatile("ldmatrix.sync.aligned.m8n8.x4.trans.shared.b16 {%0,%1,%2,%3}, [%4];"
        : "=r"(r[0]), "=r"(r[1]), "=r"(r[2]), "=r"(r[3]) : "r"(addr));
}
__device__ __forceinline__ void mma16816(float* c, const uint32_t* a,
                                         uint32_t b0, uint32_t b1) {
    asm volatile(
        "mma.sync.aligned.m16n8k16.row.col.f32.bf16.bf16.f32 "
        "{%0,%1,%2,%3}, {%4,%5,%6,%7}, {%8,%9}, {%0,%1,%2,%3};"
        : "+f"(c[0]), "+f"(c[1]), "+f"(c[2]), "+f"(c[3])
        : "r"(a[0]), "r"(a[1]), "r"(a[2]), "r"(a[3]), "r"(b0), "r"(b1));
}

// ---------------------------------------------------------------------------
// K1 (merged): blocks 0..31 fold attention vectors (one warp per output);
// blocks 32..95 split W_j into bf16 hi/lo.
// ---------------------------------------------------------------------------
__global__ void prep_kernel(const float* __restrict__ W_i,
                            const float* __restrict__ W_j,
                            const float* __restrict__ a_w,
                            const float* __restrict__ a_b) {
    if (blockIdx.x < 32) {
        int warp = blockIdx.x * 8 + (threadIdx.x >> 5);  // 0..255
        int lane = threadIdx.x & 31;
        const float* W  = (warp < 128) ? W_i : W_j;
        const float* av = (warp < 128) ? a_w : a_w + HID;
        int f = warp & 127;
        float4 w4 = ((const float4*)W)[f * 32 + lane];
        float4 a4 = ((const float4*)av)[lane];
        float s = w4.x * a4.x + w4.y * a4.y + w4.z * a4.z + w4.w * a4.w;
        #pragma unroll
        for (int o = 16; o; o >>= 1) s += __shfl_xor_sync(0xffffffffu, s, o);
        if (lane == 0) {
            if (warp < 128) g_u_i[f] = s; else g_u_j[f] = s;
        }
        if (warp == 0 && lane == 0) g_bias = a_b[0];
    } else {
        int i = (blockIdx.x - 32) * 256 + threadIdx.x;   // 16384 total
        float v = W_j[i];
        __nv_bfloat16 h = __float2bfloat16(v);
        g_wh[i] = h;
        g_wl[i] = __float2bfloat16(v - __bfloat162float(h));
    }
}

// ---------------------------------------------------------------------------
// K2: per-node scalar scores.
// ---------------------------------------------------------------------------
__global__ void score_kernel(const float* __restrict__ h_i, int N) {
    int warp = blockIdx.x * (blockDim.x >> 5) + (threadIdx.x >> 5);
    int lane = threadIdx.x & 31;
    if (warp >= N) return;
    const float4* h4 = (const float4*)h_i;
    float4 v  = h4[(size_t)warp * 32 + lane];
    float4 ui = ((const float4*)g_u_i)[lane];
    float4 uj = ((const float4*)g_u_j)[lane];
    float a = v.x * ui.x + v.y * ui.y + v.z * ui.z + v.w * ui.w;
    float b = v.x * uj.x + v.y * uj.y + v.z * uj.z + v.w * uj.w;
    #pragma unroll
    for (int o = 16; o; o >>= 1) {
        a += __shfl_xor_sync(0xffffffffu, a, o);
        b += __shfl_xor_sync(0xffffffffu, b, o);
    }
    if (lane == 0) {
        g_s_i[warp] = a;
        g_s_j[warp] = b;
    }
}

// ---------------------------------------------------------------------------
// K3 (v2): gather + softmax + weighted sum -> split bf16 A.
// One warp per node.  Software-pipelined: batches of 8 independent
// predicated LDG.128 (MLP>=8/warp) before the FMA drain.
// ---------------------------------------------------------------------------
__global__ void gather_kernel(const float* __restrict__ h_i,
                              const int* __restrict__ ctx, int N) {
    int warp = blockIdx.x * (blockDim.x >> 5) + (threadIdx.x >> 5);
    int lane = threadIdx.x & 31;
    if (warp >= N) return;

    int j = ctx[(size_t)warp * NCTX + lane];
    bool valid = (j >= 0);

    float sj = valid ? g_s_j[j] : 0.f;
    float e = g_s_i[warp] + sj + g_bias;
    e = (e > 0.f) ? e : ALPHA * e;
    e = valid ? e : NEG_INF;

    float m = e;
    #pragma unroll
    for (int o = 16; o; o >>= 1) m = fmaxf(m, __shfl_xor_sync(0xffffffffu, m, o));
    float p = valid ? __expf(e - m) : 0.f;
    float s = p;
    #pragma unroll
    for (int o = 16; o; o >>= 1) s += __shfl_xor_sync(0xffffffffu, s, o);
    float w = p * ((s > 0.f) ? (1.f / s) : 0.f);

    float4 acc = make_float4(0.f, 0.f, 0.f, 0.f);
    const float4* h4 = (const float4*)h_i;

    #pragma unroll
    for (int batch = 0; batch < 4; batch++) {
        // extract 8 (j, w) pairs, issue 8 independent loads
        int   jq[8];
        float wq[8];
        float4 vq[8];
        #pragma unroll
        for (int q = 0; q < 8; q++) {
            int c = batch * 8 + q;
            jq[q] = __shfl_sync(0xffffffffu, j, c);
            wq[q] = __shfl_sync(0xffffffffu, w, c);
        }
        #pragma unroll
        for (int q = 0; q < 8; q++) {
            vq[q] = (jq[q] >= 0) ? h4[(size_t)jq[q] * 32 + lane]
                                 : make_float4(0.f, 0.f, 0.f, 0.f);
        }
        #pragma unroll
        for (int q = 0; q < 8; q++) {
            acc.x = fmaf(wq[q], vq[q].x, acc.x);
            acc.y = fmaf(wq[q], vq[q].y, acc.y);
            acc.z = fmaf(wq[q], vq[q].z, acc.z);
            acc.w = fmaf(wq[q], vq[q].w, acc.w);
        }
    }

    __nv_bfloat16 bx = __float2bfloat16(acc.x);
    __nv_bfloat16 by = __float2bfloat16(acc.y);
    __nv_bfloat16 bz = __float2bfloat16(acc.z);
    __nv_bfloat16 bw = __float2bfloat16(acc.w);
    __nv_bfloat162* dh = (__nv_bfloat162*)&g_ah[(size_t)warp * HID + lane * 4];
    dh[0] = __halves2bfloat162(bx, by);
    dh[1] = __halves2bfloat162(bz, bw);
    __nv_bfloat162* dl = (__nv_bfloat162*)&g_al[(size_t)warp * HID + lane * 4];
    dl[0] = __halves2bfloat162(__float2bfloat16(acc.x - __bfloat162float(bx)),
                               __float2bfloat16(acc.y - __bfloat162float(by)));
    dl[1] = __halves2bfloat162(__float2bfloat16(acc.z - __bfloat162float(bz)),
                               __float2bfloat16(acc.w - __bfloat162float(bw)));
}

// ---------------------------------------------------------------------------
// K4: out = A @ W via tensor cores (bf16 split: Ah·Wh + Ah·Wl + Al·Wh).
// Block 256 thr / tile 64x128; warp tile 16x64.
// ---------------------------------------------------------------------------
__global__ __launch_bounds__(256) void mma_gemm_kernel(float* __restrict__ out,
                                                       int N) {
    __shared__ __align__(16) __nv_bfloat16 Ah_s[64][40];
    __shared__ __align__(16) __nv_bfloat16 Al_s[64][40];
    __shared__ __align__(16) __nv_bfloat16 Bh_s[32][136];
    __shared__ __align__(16) __nv_bfloat16 Bl_s[32][136];

    int row0 = blockIdx.x * 64;
    int tid  = threadIdx.x;
    int warp = tid >> 5;
    int lane = tid & 31;
    int rbase = (warp & 3) * 16;
    int cbase = (warp >> 2) * 64;

    float acc[8][4];
    #pragma unroll
    for (int t = 0; t < 8; t++)
        #pragma unroll
        for (int q = 0; q < 4; q++) acc[t][q] = 0.f;

    for (int kc = 0; kc < 4; kc++) {
        __syncthreads();
        {
            int r = tid >> 2, q = tid & 3;
            int gr = row0 + r;
            uint4 vh = make_uint4(0, 0, 0, 0), vl = vh;
            if (gr < N) {
                vh = *(const uint4*)&g_ah[(size_t)gr * HID + kc * 32 + q * 8];
                vl = *(const uint4*)&g_al[(size_t)gr * HID + kc * 32 + q * 8];
            }
            *(uint4*)&Ah_s[r][q * 8] = vh;
            *(uint4*)&Al_s[r][q * 8] = vl;
        }
        #pragma unroll
        for (int ii = tid; ii < 512; ii += 256) {
            int kr = ii >> 4, nq = ii & 15;
            *(uint4*)&Bh_s[kr][nq * 8] =
                *(const uint4*)&g_wh[(kc * 32 + kr) * HID + nq * 8];
            *(uint4*)&Bl_s[kr][nq * 8] =
                *(const uint4*)&g_wl[(kc * 32 + kr) * HID + nq * 8];
        }
        __syncthreads();

        #pragma unroll
        for (int ks = 0; ks < 2; ks++) {
            uint32_t ah[4], al[4];
            {
                int r = rbase + (lane & 15);
                int k = ks * 16 + (lane >> 4) * 8;
                ldsm_x4(ah, smem_u32(&Ah_s[r][k]));
                ldsm_x4(al, smem_u32(&Al_s[r][k]));
            }
            #pragma unroll
            for (int nt = 0; nt < 4; nt++) {
                uint32_t bh[4], bl[4];
                int k = ks * 16 + (lane & 15);
                int n = cbase + nt * 16 + (lane >> 4) * 8;
                ldsm_x4_t(bh, smem_u32(&Bh_s[k][n]));
                ldsm_x4_t(bl, smem_u32(&Bl_s[k][n]));
                mma16816(acc[2 * nt],     ah, bh[0], bh[1]);
                mma16816(acc[2 * nt],     ah, bl[0], bl[1]);
                mma16816(acc[2 * nt],     al, bh[0], bh[1]);
                mma16816(acc[2 * nt + 1], ah, bh[2], bh[3]);
                mma16816(acc[2 * nt + 1], ah, bl[2], bl[3]);
                mma16816(acc[2 * nt + 1], al, bh[2], bh[3]);
            }
        }
    }

    int gid = lane >> 2, tig = lane & 3;
    #pragma unroll
    for (int t = 0; t < 8; t++) {
        int c  = cbase + t * 8 + tig * 2;
        int r1 = row0 + rbase + gid;
        int r2 = r1 + 8;
        if (r1 < N) *(float2*)&out[(size_t)r1 * 128 + c] = make_float2(acc[t][0], acc[t][1]);
        if (r2 < N) *(float2*)&out[(size_t)r2 * 128 + c] = make_float2(acc[t][2], acc[t][3]);
    }
}

// ---------------------------------------------------------------------------
extern "C" void kernel_launch(void* const* d_in, const int* in_sizes, int n_in,
                              void* d_out, int out_size) {
    const float* h_i = (const float*)d_in[0];
    const int*   ctx = (const int*)d_in[1];     // int32
    const float* W_i = (const float*)d_in[2];
    const float* W_j = (const float*)d_in[3];
    const float* a_w = (const float*)d_in[4];
    const float* a_b = (const float*)d_in[5];
    float* out = (float*)d_out;

    int N = in_sizes[0] / IN_F;

    prep_kernel<<<96, 256>>>(W_i, W_j, a_w, a_b);   // fold + W split merged

    int blocks = (N + 7) / 8;
    score_kernel<<<blocks, 256>>>(h_i, N);
    gather_kernel<<<blocks, 256>>>(h_i, ctx, N);

    int gemm_blocks = (N + 63) / 64;
    mma_gemm_kernel<<<gemm_blocks, 256>>>(out, N);
}

// round 12
// speedup vs baseline: 1.7731x; 1.2726x over previous
#include <cuda_runtime.h>
#include <cuda_bf16.h>
#include <cuda_fp16.h>
#include <cstdint>

#define IN_F 128
#define HID 128
#define NCTX 32
#define ALPHA 0.2f
#define NEG_INF -9000000000000000.0f
#define MAXN 20000
#define MAXR 20032   // MAXN rounded up to 64

// Scratch (device globals — no allocation allowed)
__device__ __align__(16) float g_u_i[IN_F];
__device__ __align__(16) float g_u_j[IN_F];
__device__ float g_bias;
__device__ float g_s_i[MAXN];
__device__ float g_s_j[MAXN];
__device__ __align__(16) __half g_hf16[(size_t)MAXN * IN_F];   // fp16 feature table
__device__ __align__(16) __half g_af16[(size_t)MAXR * HID];    // fp16 A (weighted sums)
__device__ __align__(16) __half g_wf16[HID * HID];             // fp16 W_j

// ---------------------------------------------------------------------------
// mma/ldmatrix helpers
// ---------------------------------------------------------------------------
__device__ __forceinline__ uint32_t smem_u32(const void* p) {
    return (uint32_t)__cvta_generic_to_shared(p);
}
__device__ __forceinline__ void ldsm_x4(uint32_t* r, uint32_t addr) {
    asm volatile("ldmatrix.sync.aligned.m8n8.x4.shared.b16 {%0,%1,%2,%3}, [%4];"
        : "=r"(r[0]), "=r"(r[1]), "=r"(r[2]), "=r"(r[3]) : "r"(addr));
}
__device__ __forceinline__ void ldsm_x4_t(uint32_t* r, uint32_t addr) {
    asm volatile("ldmatrix.sync.aligned.m8n8.x4.trans.shared.b16 {%0,%1,%2,%3}, [%4];"
        : "=r"(r[0]), "=r"(r[1]), "=r"(r[2]), "=r"(r[3]) : "r"(addr));
}
__device__ __forceinline__ void mma16816h(float* c, const uint32_t* a,
                                          uint32_t b0, uint32_t b1) {
    asm volatile(
        "mma.sync.aligned.m16n8k16.row.col.f32.f16.f16.f32 "
        "{%0,%1,%2,%3}, {%4,%5,%6,%7}, {%8,%9}, {%0,%1,%2,%3};"
        : "+f"(c[0]), "+f"(c[1]), "+f"(c[2]), "+f"(c[3])
        : "r"(a[0]), "r"(a[1]), "r"(a[2]), "r"(a[3]), "r"(b0), "r"(b1));
}

// ---------------------------------------------------------------------------
// K1 (merged): blocks 0..31 fold attention vectors (one warp per output);
// blocks 32..95 convert W_j to fp16.
// ---------------------------------------------------------------------------
__global__ void prep_kernel(const float* __restrict__ W_i,
                            const float* __restrict__ W_j,
                            const float* __restrict__ a_w,
                            const float* __restrict__ a_b) {
    if (blockIdx.x < 32) {
        int warp = blockIdx.x * 8 + (threadIdx.x >> 5);  // 0..255
        int lane = threadIdx.x & 31;
        const float* W  = (warp < 128) ? W_i : W_j;
        const float* av = (warp < 128) ? a_w : a_w + HID;
        int f = warp & 127;
        float4 w4 = ((const float4*)W)[f * 32 + lane];
        float4 a4 = ((const float4*)av)[lane];
        float s = w4.x * a4.x + w4.y * a4.y + w4.z * a4.z + w4.w * a4.w;
        #pragma unroll
        for (int o = 16; o; o >>= 1) s += __shfl_xor_sync(0xffffffffu, s, o);
        if (lane == 0) {
            if (warp < 128) g_u_i[f] = s; else g_u_j[f] = s;
        }
        if (warp == 0 && lane == 0) g_bias = a_b[0];
    } else {
        int i = (blockIdx.x - 32) * 256 + threadIdx.x;   // 16384 total
        g_wf16[i] = __float2half(W_j[i]);
    }
}

// ---------------------------------------------------------------------------
// K2: per-node scalar scores + build fp16 feature table (same h_i pass).
// ---------------------------------------------------------------------------
__global__ void score_kernel(const float* __restrict__ h_i, int N) {
    int warp = blockIdx.x * (blockDim.x >> 5) + (threadIdx.x >> 5);
    int lane = threadIdx.x & 31;
    if (warp >= N) return;
    const float4* h4 = (const float4*)h_i;
    float4 v  = h4[(size_t)warp * 32 + lane];
    float4 ui = ((const float4*)g_u_i)[lane];
    float4 uj = ((const float4*)g_u_j)[lane];

    // fp16 table write (coalesced 8B/lane)
    __half2 p0 = __floats2half2_rn(v.x, v.y);
    __half2 p1 = __floats2half2_rn(v.z, v.w);
    *(uint2*)&g_hf16[(size_t)warp * IN_F + lane * 4] =
        make_uint2(*(uint32_t*)&p0, *(uint32_t*)&p1);

    float a = v.x * ui.x + v.y * ui.y + v.z * ui.z + v.w * ui.w;
    float b = v.x * uj.x + v.y * uj.y + v.z * uj.z + v.w * uj.w;
    #pragma unroll
    for (int o = 16; o; o >>= 1) {
        a += __shfl_xor_sync(0xffffffffu, a, o);
        b += __shfl_xor_sync(0xffffffffu, b, o);
    }
    if (lane == 0) {
        g_s_i[warp] = a;
        g_s_j[warp] = b;
    }
}

// ---------------------------------------------------------------------------
// K3: gather (fp16 table) + softmax + weighted sum -> fp16 A.
// One warp per node; batches of 8 independent LDG.64.
// ---------------------------------------------------------------------------
__global__ void gather_kernel(const int* __restrict__ ctx, int N) {
    int warp = blockIdx.x * (blockDim.x >> 5) + (threadIdx.x >> 5);
    int lane = threadIdx.x & 31;
    if (warp >= N) return;

    int j = ctx[(size_t)warp * NCTX + lane];
    bool valid = (j >= 0);

    float sj = valid ? g_s_j[j] : 0.f;
    float e = g_s_i[warp] + sj + g_bias;
    e = (e > 0.f) ? e : ALPHA * e;
    e = valid ? e : NEG_INF;

    float m = e;
    #pragma unroll
    for (int o = 16; o; o >>= 1) m = fmaxf(m, __shfl_xor_sync(0xffffffffu, m, o));
    float p = valid ? __expf(e - m) : 0.f;
    float s = p;
    #pragma unroll
    for (int o = 16; o; o >>= 1) s += __shfl_xor_sync(0xffffffffu, s, o);
    float w = p * ((s > 0.f) ? (1.f / s) : 0.f);

    float4 acc = make_float4(0.f, 0.f, 0.f, 0.f);
    const uint2* hrow = (const uint2*)g_hf16;   // 4 halves per uint2; 32/row

    #pragma unroll
    for (int batch = 0; batch < 4; batch++) {
        int   jq[8];
        float wq[8];
        uint2 vq[8];
        #pragma unroll
        for (int q = 0; q < 8; q++) {
            int c = batch * 8 + q;
            jq[q] = __shfl_sync(0xffffffffu, j, c);
            wq[q] = __shfl_sync(0xffffffffu, w, c);
        }
        #pragma unroll
        for (int q = 0; q < 8; q++) {
            vq[q] = (jq[q] >= 0) ? hrow[(size_t)jq[q] * 32 + lane]
                                 : make_uint2(0u, 0u);
        }
        #pragma unroll
        for (int q = 0; q < 8; q++) {
            float2 f0 = __half22float2(*(__half2*)&vq[q].x);
            float2 f1 = __half22float2(*(__half2*)&vq[q].y);
            acc.x = fmaf(wq[q], f0.x, acc.x);
            acc.y = fmaf(wq[q], f0.y, acc.y);
            acc.z = fmaf(wq[q], f1.x, acc.z);
            acc.w = fmaf(wq[q], f1.y, acc.w);
        }
    }

    __half2 o0 = __floats2half2_rn(acc.x, acc.y);
    __half2 o1 = __floats2half2_rn(acc.z, acc.w);
    *(uint2*)&g_af16[(size_t)warp * HID + lane * 4] =
        make_uint2(*(uint32_t*)&o0, *(uint32_t*)&o1);
}

// ---------------------------------------------------------------------------
// K4: out = A @ W via fp16 tensor cores (single term).
// Block 128 thr / 4 warps, tile 32 rows x 128 cols; warp tile 16x64.
// grid = 625 -> ~17 warps/SM.
// ---------------------------------------------------------------------------
__global__ __launch_bounds__(128) void mma_gemm_kernel(float* __restrict__ out,
                                                       int N) {
    __shared__ __align__(16) __half As[32][40];    // 2.5KB, pad 8
    __shared__ __align__(16) __half Bs[32][136];   // 8.5KB, pad 8

    int row0 = blockIdx.x * 32;
    int tid  = threadIdx.x;
    int warp = tid >> 5;
    int lane = tid & 31;
    int rbase = (warp & 1) * 16;
    int cbase = (warp >> 1) * 64;

    float acc[8][4];
    #pragma unroll
    for (int t = 0; t < 8; t++)
        #pragma unroll
        for (int q = 0; q < 4; q++) acc[t][q] = 0.f;

    for (int kc = 0; kc < 4; kc++) {
        __syncthreads();
        // A chunk: 32 rows x 32 k. thread: row=tid>>2, 8 halves at (tid&3)*8.
        {
            int r = tid >> 2, q = tid & 3;
            int gr = row0 + r;
            uint4 v = make_uint4(0, 0, 0, 0);
            if (gr < N) v = *(const uint4*)&g_af16[(size_t)gr * HID + kc * 32 + q * 8];
            *(uint4*)&As[r][q * 8] = v;
        }
        // B chunk: 32 k-rows x 128 n.  512 uint4 / 128 thr = 4 each.
        #pragma unroll
        for (int ii = tid; ii < 512; ii += 128) {
            int kr = ii >> 4, nq = ii & 15;
            *(uint4*)&Bs[kr][nq * 8] =
                *(const uint4*)&g_wf16[(kc * 32 + kr) * HID + nq * 8];
        }
        __syncthreads();

        #pragma unroll
        for (int ks = 0; ks < 2; ks++) {
            uint32_t af[4];
            {
                int r = rbase + (lane & 15);
                int k = ks * 16 + (lane >> 4) * 8;
                ldsm_x4(af, smem_u32(&As[r][k]));
            }
            #pragma unroll
            for (int nt = 0; nt < 4; nt++) {
                uint32_t bf[4];
                int k = ks * 16 + (lane & 15);
                int n = cbase + nt * 16 + (lane >> 4) * 8;
                ldsm_x4_t(bf, smem_u32(&Bs[k][n]));
                mma16816h(acc[2 * nt],     af, bf[0], bf[1]);
                mma16816h(acc[2 * nt + 1], af, bf[2], bf[3]);
            }
        }
    }

    int gid = lane >> 2, tig = lane & 3;
    #pragma unroll
    for (int t = 0; t < 8; t++) {
        int c  = cbase + t * 8 + tig * 2;
        int r1 = row0 + rbase + gid;
        int r2 = r1 + 8;
        if (r1 < N) *(float2*)&out[(size_t)r1 * 128 + c] = make_float2(acc[t][0], acc[t][1]);
        if (r2 < N) *(float2*)&out[(size_t)r2 * 128 + c] = make_float2(acc[t][2], acc[t][3]);
    }
}

// ---------------------------------------------------------------------------
extern "C" void kernel_launch(void* const* d_in, const int* in_sizes, int n_in,
                              void* d_out, int out_size) {
    const float* h_i = (const float*)d_in[0];
    const int*   ctx = (const int*)d_in[1];     // int32
    const float* W_i = (const float*)d_in[2];
    const float* W_j = (const float*)d_in[3];
    const float* a_w = (const float*)d_in[4];
    const float* a_b = (const float*)d_in[5];
    float* out = (float*)d_out;

    int N = in_sizes[0] / IN_F;

    prep_kernel<<<96, 256>>>(W_i, W_j, a_w, a_b);

    int blocks = (N + 7) / 8;
    score_kernel<<<blocks, 256>>>(h_i, N);
    gather_kernel<<<blocks, 256>>>(ctx, N);

    int gemm_blocks = (N + 31) / 32;
    mma_gemm_kernel<<<gemm_blocks, 128>>>(out, N);
}